// round 7
// baseline (speedup 1.0000x reference)
#include <cuda_runtime.h>

// VolSDF volume renderer.
// Inputs: distance [M,128,1] f32, color [M,128,3] f32, depth_values [M,128] f32
// Output: out_color [M,3] f32 followed by geometry [M,3] f32 (zeros).
//
// One warp per TWO rays; lane l owns samples [4l, 4l+4) of each ray. All 10
// LDG.128 per thread are issued up front (MLP=10) before any compute.
//
// Sample 127 carries the FAR_DELTA=1e10 sentinel; the reference's float32
// cumsum is a BLOCKED scan (chunk=16): cs127 = fl(S[0:112) + fl(S[112:127) +
// sd127)). Replicated exactly (validated rel_err 8e-8).

#define FAR_DELTA_ 1e10f

__device__ __forceinline__ float sdf_density(float d) {
    float s = -d;
    float a = fabsf(s) / 0.05f;
    float e = expf(-a);
    return (s <= 0.0f) ? __fmul_rn(10.0f, __fmul_rn(0.5f, e))
                       : __fmul_rn(10.0f, __fsub_rn(1.0f, __fmul_rn(0.5f, e)));
}

__device__ __forceinline__ void render_step(float& run, float sd,
                                            float cr, float cg, float cb,
                                            float& r, float& g, float& b) {
    float inc = __fadd_rn(run, sd);
    float T   = expf(-__fsub_rn(inc, sd));
    float w   = T * (1.0f - expf(-sd));
    run = inc;
    r += w * cr; g += w * cg; b += w * cb;
}

// Full per-ray pipeline: scan + weights + RGB reduce + store (lane 0).
__device__ __forceinline__ void process_ray(
    int lane, long long ray,
    const float4& d4, const float4& z4,
    const float4& c0, const float4& c1, const float4& c2,
    float* __restrict__ out)
{
    const unsigned FULL = 0xffffffffu;

    const float z_next = __shfl_down_sync(FULL, z4.x, 1);

    const float del0 = __fsub_rn(z4.y, z4.x);
    const float del1 = __fsub_rn(z4.z, z4.y);
    const float del2 = __fsub_rn(z4.w, z4.z);
    const float del3 = (lane == 31) ? FAR_DELTA_ : __fsub_rn(z_next, z4.w);

    const float sd0 = __fmul_rn(sdf_density(d4.x), del0);
    const float sd1 = __fmul_rn(sdf_density(d4.y), del1);
    const float sd2 = __fmul_rn(sdf_density(d4.z), del2);
    const float sd3 = __fmul_rn(sdf_density(d4.w), del3);

    const float lsum = __fadd_rn(__fadd_rn(__fadd_rn(sd0, sd1), sd2), sd3);

    // warp inclusive scan (Kogge-Stone)
    float x = lsum;
    #pragma unroll
    for (int off = 1; off < 32; off <<= 1) {
        float y = __shfl_up_sync(FULL, x, off);
        if (lane >= off) x += y;
    }
    // exclusive prefix via shfl (lane 31's lsum is ~1e11: never subtract)
    float run = __shfl_up_sync(FULL, x, 1);
    if (lane == 0) run = 0.0f;

    const float x27 = __shfl_sync(FULL, x, 27);   // S[0:112)
    const float x30 = __shfl_sync(FULL, x, 30);   // S[0:124)

    float r = 0.0f, g = 0.0f, b = 0.0f;
    render_step(run, sd0, c0.x, c0.y, c0.z, r, g, b);
    render_step(run, sd1, c0.w, c1.x, c1.y, r, g, b);
    render_step(run, sd2, c1.z, c1.w, c2.x, r, g, b);

    if (lane != 31) {
        render_step(run, sd3, c2.y, c2.z, c2.w, r, g, b);
    } else {
        // Blocked scan, chunk 16: local chunk = samples [112,128).
        const float Lloc  = __fadd_rn(__fsub_rn(x30, x27),
                                      __fadd_rn(__fadd_rn(sd0, sd1), sd2));
        const float local = __fadd_rn(Lloc, sd3);
        const float cs    = __fadd_rn(x27, local);
        const float q     = __fsub_rn(cs, sd3);
        const float T     = expf(-q);
        const float w     = T * (1.0f - expf(-sd3));
        r += w * c2.y; g += w * c2.z; b += w * c2.w;
    }

    #pragma unroll
    for (int off = 16; off > 0; off >>= 1) {
        r += __shfl_xor_sync(FULL, r, off);
        g += __shfl_xor_sync(FULL, g, off);
        b += __shfl_xor_sync(FULL, b, off);
    }

    if (lane == 0) {
        out[ray * 3 + 0] = r;
        out[ray * 3 + 1] = g;
        out[ray * 3 + 2] = b;
    }
}

__global__ void __launch_bounds__(256) volsdf_render_kernel(
    const float* __restrict__ dist,
    const float* __restrict__ color,
    const float* __restrict__ depth,
    float* __restrict__ out,
    int M)
{
    const int gtid = blockIdx.x * blockDim.x + threadIdx.x;
    const int lane = gtid & 31;
    const long long ray0 = (long long)(gtid >> 5) * 2;
    if (ray0 >= M) return;
    const bool has1 = (ray0 + 1) < M;

    const long long baseA = ray0 * 128;
    const long long baseB = baseA + 128;
    const long long cbA   = baseA * 3 + (long long)lane * 12;
    const long long cbB   = cbA + 384;

    // ---- issue ALL loads up front: 10 independent LDG.128 per thread ----
    const float4 d4A = *reinterpret_cast<const float4*>(dist  + baseA + lane * 4);
    const float4 z4A = *reinterpret_cast<const float4*>(depth + baseA + lane * 4);
    const float4 c0A = *reinterpret_cast<const float4*>(color + cbA + 0);
    const float4 c1A = *reinterpret_cast<const float4*>(color + cbA + 4);
    const float4 c2A = *reinterpret_cast<const float4*>(color + cbA + 8);

    float4 d4B = make_float4(0,0,0,0), z4B = make_float4(0,0,0,0);
    float4 c0B = make_float4(0,0,0,0), c1B = make_float4(0,0,0,0), c2B = make_float4(0,0,0,0);
    if (has1) {
        d4B = *reinterpret_cast<const float4*>(dist  + baseB + lane * 4);
        z4B = *reinterpret_cast<const float4*>(depth + baseB + lane * 4);
        c0B = *reinterpret_cast<const float4*>(color + cbB + 0);
        c1B = *reinterpret_cast<const float4*>(color + cbB + 4);
        c2B = *reinterpret_cast<const float4*>(color + cbB + 8);
    }

    // geometry output zeros, overlapped with in-flight loads
    if (lane == 1) {
        const long long gb = (long long)M * 3 + ray0 * 3;
        out[gb + 0] = 0.0f; out[gb + 1] = 0.0f; out[gb + 2] = 0.0f;
        if (has1) { out[gb + 3] = 0.0f; out[gb + 4] = 0.0f; out[gb + 5] = 0.0f; }
    }

    process_ray(lane, ray0, d4A, z4A, c0A, c1A, c2A, out);
    if (has1)
        process_ray(lane, ray0 + 1, d4B, z4B, c0B, c1B, c2B, out);
}

extern "C" void kernel_launch(void* const* d_in, const int* in_sizes, int n_in,
                              void* d_out, int out_size) {
    const float* dist  = (const float*)d_in[0];   // [M,128,1]
    const float* color = (const float*)d_in[1];   // [M,128,3]
    const float* depth = (const float*)d_in[2];   // [M,128]

    const int M = in_sizes[2] / 128;
    float* out = (float*)d_out;

    // Kernel writes out_color and geometry zeros; memset only any tail beyond.
    const long long expected = (long long)M * 6;
    if ((long long)out_size > expected) {
        cudaMemsetAsync(out + expected, 0,
                        ((long long)out_size - expected) * sizeof(float), 0);
    }

    const int threads = 256;                 // 8 warps -> 16 rays per block
    const int rays_per_block = 16;
    const int blocks = (M + rays_per_block - 1) / rays_per_block;
    volsdf_render_kernel<<<blocks, threads>>>(dist, color, depth, out, M);
}